// round 13
// baseline (speedup 1.0000x reference)
#include <cuda_runtime.h>
#include <cuda_fp16.h>
#include <math.h>
#include <stdint.h>

#define BATCH 8
#define NN    2048
#define FIN   256
#define FOUT  64
#define LALPHA 0.2f

// ---------------- scratch (__device__ globals) -----------------------------
__device__ float  g_Wh[BATCH * NN * FOUT];      // 4 MB fp32 (for e-factors)
__device__ __half g_Whh[BATCH * NN * FOUT];     // 2 MB  [b][j][o] hi
__device__ __half g_Whl[BATCH * NN * FOUT];     // 2 MB  [b][j][o] lo
__device__ float  g_e1[BATCH * NN];
__device__ float2 g_BD[BATCH * NN];             // (exp(e2), exp(0.2*e2))
__device__ float  g_pmax[64];

// ---------------- PTX helpers ----------------------------------------------
__device__ __forceinline__ uint32_t smem_u32(const void* p) {
    uint32_t a;
    asm("{ .reg .u64 t; cvta.to.shared.u64 t, %1; cvt.u32.u64 %0, t; }" : "=r"(a) : "l"(p));
    return a;
}
__device__ __forceinline__ void ldsm_x4(uint32_t* r, uint32_t a) {
    asm volatile("ldmatrix.sync.aligned.m8n8.x4.shared.b16 {%0,%1,%2,%3}, [%4];"
                 : "=r"(r[0]), "=r"(r[1]), "=r"(r[2]), "=r"(r[3]) : "r"(a));
}
__device__ __forceinline__ void ldsm_x4_t(uint32_t* r, uint32_t a) {
    asm volatile("ldmatrix.sync.aligned.m8n8.x4.trans.shared.b16 {%0,%1,%2,%3}, [%4];"
                 : "=r"(r[0]), "=r"(r[1]), "=r"(r[2]), "=r"(r[3]) : "r"(a));
}
__device__ __forceinline__ void mma16816(float* c, const uint32_t* a,
                                         uint32_t b0, uint32_t b1) {
    asm volatile("mma.sync.aligned.m16n8k16.row.col.f32.f16.f16.f32 "
                 "{%0,%1,%2,%3}, {%4,%5,%6,%7}, {%8,%9}, {%0,%1,%2,%3};"
                 : "+f"(c[0]), "+f"(c[1]), "+f"(c[2]), "+f"(c[3])
                 : "r"(a[0]), "r"(a[1]), "r"(a[2]), "r"(a[3]), "r"(b0), "r"(b1));
}
__device__ __forceinline__ void cp_async16(uint32_t dst, const void* src) {
    asm volatile("cp.async.ca.shared.global [%0], [%1], 16;" :: "r"(dst), "l"(src));
}

// ---------------------------------------------------------------------------
// Kernel A: Wh = h @ W^T  (16384x64x256). 64-row tiles, 256 threads, grid 256.
// ---------------------------------------------------------------------------
#define AK 32
__global__ __launch_bounds__(256) void wh_gemm(const float* __restrict__ h,
                                               const float* __restrict__ W) {
    __shared__ float shT[AK][68];
    __shared__ float sWT[AK][68];
    const int t    = threadIdx.x;
    const int row0 = blockIdx.x * 64;
    const int rg   = t >> 4;
    const int cgA  = t & 15;

    float acc[4][4];
#pragma unroll
    for (int r = 0; r < 4; r++)
#pragma unroll
        for (int c = 0; c < 4; c++) acc[r][c] = 0.f;

    for (int k0 = 0; k0 < FIN; k0 += AK) {
        __syncthreads();
        int idx = t;
#pragma unroll
        for (int u = 0; u < 2; u++, idx += 256) {
            int r = idx >> 3, kq = idx & 7;
            float4 v = *(const float4*)(h + (size_t)(row0 + r) * FIN + k0 + kq * 4);
            shT[kq*4+0][r] = v.x; shT[kq*4+1][r] = v.y;
            shT[kq*4+2][r] = v.z; shT[kq*4+3][r] = v.w;
        }
        idx = t;
#pragma unroll
        for (int u = 0; u < 2; u++, idx += 256) {
            int o = idx >> 3, kq = idx & 7;
            float4 v = *(const float4*)(W + (size_t)o * FIN + k0 + kq * 4);
            sWT[kq*4+0][o] = v.x; sWT[kq*4+1][o] = v.y;
            sWT[kq*4+2][o] = v.z; sWT[kq*4+3][o] = v.w;
        }
        __syncthreads();

#pragma unroll
        for (int k = 0; k < AK; k++) {
            float4 hv = *(const float4*)&shT[k][rg * 4];
            float4 wv = *(const float4*)&sWT[k][cgA * 4];
            float hr[4] = {hv.x, hv.y, hv.z, hv.w};
            float wc[4] = {wv.x, wv.y, wv.z, wv.w};
#pragma unroll
            for (int r = 0; r < 4; r++)
#pragma unroll
                for (int c = 0; c < 4; c++) acc[r][c] = fmaf(hr[r], wc[c], acc[r][c]);
        }
    }

#pragma unroll
    for (int r = 0; r < 4; r++) {
        const size_t row = row0 + rg * 4 + r;
        *(float4*)(g_Wh + row * FOUT + cgA * 4) =
            make_float4(acc[r][0], acc[r][1], acc[r][2], acc[r][3]);
        __half2 h01 = __float22half2_rn(make_float2(acc[r][0], acc[r][1]));
        __half2 h23 = __float22half2_rn(make_float2(acc[r][2], acc[r][3]));
        float2 f01 = __half22float2(h01);
        float2 f23 = __half22float2(h23);
        __half2 l01 = __float22half2_rn(make_float2(acc[r][0]-f01.x, acc[r][1]-f01.y));
        __half2 l23 = __float22half2_rn(make_float2(acc[r][2]-f23.x, acc[r][3]-f23.y));
        *(uint2*)(g_Whh + row * FOUT + cgA * 4) = make_uint2(*(unsigned*)&h01, *(unsigned*)&h23);
        *(uint2*)(g_Whl + row * FOUT + cgA * 4) = make_uint2(*(unsigned*)&l01, *(unsigned*)&l23);
    }
}

// ---------------------------------------------------------------------------
// Kernel E: e1, (B,D)=exp factors, partial max(e2). 64 blocks, 256 threads.
// ---------------------------------------------------------------------------
__global__ __launch_bounds__(256) void e_kernel(const float* __restrict__ a) {
    const int blk = blockIdx.x, t = threadIdx.x;
    const int bb = blk >> 3, ch = blk & 7;
    __shared__ float sa1[FOUT], sa2[FOUT], smax[256];
    if (t < FOUT) sa1[t] = a[t];
    else if (t < 2 * FOUT) sa2[t - FOUT] = a[t];
    __syncthreads();

    const int row = bb * NN + ch * 256 + t;
    const float4* wh = (const float4*)(g_Wh + (size_t)row * FOUT);
    float e1 = 0.f, e2 = 0.f;
#pragma unroll
    for (int q = 0; q < 16; q++) {
        float4 v = wh[q];
        e1 = fmaf(v.x, sa1[q*4+0], fmaf(v.y, sa1[q*4+1], fmaf(v.z, sa1[q*4+2], fmaf(v.w, sa1[q*4+3], e1))));
        e2 = fmaf(v.x, sa2[q*4+0], fmaf(v.y, sa2[q*4+1], fmaf(v.z, sa2[q*4+2], fmaf(v.w, sa2[q*4+3], e2))));
    }
    g_e1[row] = e1;
    g_BD[row] = make_float2(__expf(e2), __expf(LALPHA * e2));
    smax[t] = e2; __syncthreads();
    for (int s = 128; s > 0; s >>= 1) {
        if (t < s) smax[t] = fmaxf(smax[t], smax[t + s]);
        __syncthreads();
    }
    if (t == 0) g_pmax[blk] = smax[0];
}

// ---------------------------------------------------------------------------
// Kernel C: fused masked softmax @ Wh via mma.sync.
// adj is packed in-block into a 16KB smem bitmask (pipelined, 4 chunks of
// 512 j); Wh tiles double-buffered via cp.async. No DRAM access in the
// compute path except the overlapped pack stream.
// Block = (b, 64-row tile): grid (32,8)=256, 512 thr, 2 blocks/SM.
// ---------------------------------------------------------------------------
#define PH_OFF   0               // P fp16 tile: 64 x 72 halves  = 9216 B
#define WH_OFF   9216            // 2 bufs x (hi 9216 + lo 9216) = 36864 B
#define BD_OFF   46080           // 1024 float4 (2048 float2)    = 16384 B
#define BITS_OFF 62464           // 64 rows x 272 B              = 17408 B
#define L_OFF    79872           // 64 floats
#define SMEM_SZ  80384

__global__ __launch_bounds__(512, 2) void attn_mma(const int* __restrict__ adj,
                                                   float* __restrict__ out) {
    extern __shared__ char smem[];
    const uint32_t sb = smem_u32(smem);

    const int t    = threadIdx.x;
    const int wid  = t >> 5;
    const int lane = t & 31;
    const int b    = blockIdx.y;
    const int i0   = blockIdx.x * 64;

    // P-phase mapping: 8 threads per row, 8 j each
    const int prow = t >> 3;
    const int oct  = t & 7;

    {   // (B,D) factors of this batch -> smem (1024 float4, 512 threads: 2 each)
        const float4* src = (const float4*)(g_BD + (size_t)b * NN);
        float4* dst = (float4*)(smem + BD_OFF);
#pragma unroll
        for (int u = 0; u < 2; u++) dst[t + u * 512] = src[t + u * 512];
    }
    const float e1r = g_e1[b * NN + i0 + prow];
    float e2m = -3.0e38f;
#pragma unroll
    for (int k = 0; k < 8; k++) e2m = fmaxf(e2m, g_pmax[b * 8 + k]);
    float Mr = e1r + e2m;
    Mr = (Mr > 0.f) ? Mr : LALPHA * Mr;
    const float Ar = __expf(e1r - Mr);
    const float Cr = __expf(LALPHA * e1r - Mr);
    const float Tr = __expf(-e1r);

    // ---- pack chunk 0 of adj into smem bitmask (warp w: rows 4w..4w+3) ----
    {
#pragma unroll 1
        for (int kb = 0; kb < 64; kb += 8) {
            int pk[8];
#pragma unroll
            for (int m = 0; m < 8; m++) {
                int k = kb + m;
                pk[m] = adj[(size_t)(b*NN + i0 + wid*4 + (k >> 4)) * NN + (k & 15) * 32 + lane];
            }
#pragma unroll
            for (int m = 0; m < 8; m++) {
                int k = kb + m;
                uint32_t msk = __ballot_sync(0xffffffffu, pk[m] > 0);
                if (lane == 0)
                    *(uint32_t*)(smem + BITS_OFF + (wid*4 + (k >> 4)) * 272 + (k & 15) * 4) = msk;
            }
        }
    }

    // Wh fill mapping: wjr = row 0..63, wjc = col octet
    const int wjr = t >> 3;
    const int wjc = (t & 7) * 8;
    const uint32_t wh_sdst = (uint32_t)((wjr * 72 + wjc) * 2);

    {   // cp.async Wh tile 0 -> buf 0
        const size_t gsrc = ((size_t)(b * NN) + wjr) * FOUT + wjc;
        cp_async16(sb + WH_OFF + wh_sdst,        g_Whh + gsrc);
        cp_async16(sb + WH_OFF + wh_sdst + 9216, g_Whl + gsrc);
        asm volatile("cp.async.commit_group;");
    }

    float acc[2][4];
#pragma unroll
    for (int g = 0; g < 2; g++)
#pragma unroll
        for (int q = 0; q < 4; q++) acc[g][q] = 0.f;
    float lpart = 0.f;

    // mma-phase address components (warp: 16-row slab x 16-col quarter)
    const int slab = wid >> 2;
    const int nq   = wid & 3;
    const int rb   = slab * 16;
    const int m8 = lane >> 3, r8 = lane & 7;
    const uint32_t a_off = (uint32_t)(((rb + r8 + 8 * (m8 & 1)) * 72 + 8 * (m8 >> 1)) * 2);
    const uint32_t b_off = (uint32_t)(((r8 + 8 * (m8 & 1)) * 72 + 8 * (m8 >> 1)) * 2);
    const uint32_t p_off = (uint32_t)((prow * 72 + oct * 8) * 2);

    __syncthreads();

    for (int jt = 0; jt < 32; jt++) {
        const int j0 = jt * 64;
        const int s  = jt & 1;
        const int c  = (jt >> 3) + 1;          // chunk being prefetched
        const int kbase = (jt & 7) * 8;

        // ---- 1. issue pack loads for next chunk (8 LDG.32, coalesced) ----
        int pk[8];
        if (c < 4) {
#pragma unroll
            for (int m = 0; m < 8; m++) {
                int k = kbase + m;
                pk[m] = adj[(size_t)(b*NN + i0 + wid*4 + (k >> 4)) * NN
                            + c * 512 + (k & 15) * 32 + lane];
            }
        }

        // ---- 2. cp.async next Wh tile ----
        if (jt < 31) {
            const size_t gsrc = ((size_t)(b * NN) + (jt + 1) * 64 + wjr) * FOUT + wjc;
            const uint32_t dst = sb + WH_OFF + ((jt + 1) & 1) * 18432 + wh_sdst;
            cp_async16(dst,        g_Whh + gsrc);
            cp_async16(dst + 9216, g_Whl + gsrc);
            asm volatile("cp.async.commit_group;");
        }

        // ---- 3. P phase: 8 probs (no exp, mask = smem bit) ----
        {
            const uint32_t mbyte =
                *(const unsigned char*)(smem + BITS_OFF + prow * 272 + jt * 8 + oct);
            const float4* bdq = (const float4*)(smem + BD_OFF) + (j0 >> 1) + oct * 4;
            float pq[8];
#pragma unroll
            for (int cc = 0; cc < 2; cc++) {
                float4 bd0 = bdq[cc * 2];
                float4 bd1 = bdq[cc * 2 + 1];
                float Bv[4] = {bd0.x, bd0.z, bd1.x, bd1.z};
                float Dv[4] = {bd0.y, bd0.w, bd1.y, bd1.w};
#pragma unroll
                for (int q = 0; q < 4; q++) {
                    bool hi = Bv[q] > Tr;
                    float p = (hi ? Ar : Cr) * (hi ? Bv[q] : Dv[q]);
                    p = ((mbyte >> (cc * 4 + q)) & 1) ? p : 0.f;
                    pq[cc * 4 + q] = p;
                    lpart += p;
                }
            }
            unsigned vh[4];
#pragma unroll
            for (int q = 0; q < 4; q++) {
                __half2 hh = __float22half2_rn(make_float2(pq[2*q], pq[2*q+1]));
                vh[q] = *(unsigned*)&hh;
            }
            *(uint4*)(smem + PH_OFF + p_off) = make_uint4(vh[0], vh[1], vh[2], vh[3]);
        }

        // ---- 4. ballots for next chunk -> bitmask smem ----
        if (c < 4) {
#pragma unroll
            for (int m = 0; m < 8; m++) {
                int k = kbase + m;
                uint32_t msk = __ballot_sync(0xffffffffu, pk[m] > 0);
                if (lane == 0)
                    *(uint32_t*)(smem + BITS_OFF + (wid*4 + (k >> 4)) * 272
                                 + (c * 16 + (k & 15)) * 4) = msk;
            }
        }

        // ---- 5. wait Wh[jt], barrier ----
        if (jt < 31) asm volatile("cp.async.wait_group 1;");
        else         asm volatile("cp.async.wait_group 0;");
        __syncthreads();

        // ---- 6. mma phase: 4 k-chunks x 1 n-quarter x 2 terms ----
        const uint32_t whh = sb + WH_OFF + s * 18432;
#pragma unroll
        for (int kk = 0; kk < 4; kk++) {
            uint32_t ah[4];
            ldsm_x4(ah, sb + PH_OFF + a_off + kk * 32);
            uint32_t bh[4], bl[4];
            const uint32_t boff = b_off + kk * (16 * 144) + nq * 32;
            ldsm_x4_t(bh, whh + boff);
            ldsm_x4_t(bl, whh + 9216 + boff);
            mma16816(acc[0], ah, bh[0], bh[1]);
            mma16816(acc[0], ah, bl[0], bl[1]);
            mma16816(acc[1], ah, bh[2], bh[3]);
            mma16816(acc[1], ah, bl[2], bl[3]);
        }
        __syncthreads();
    }

    // ---- denominators: reduce over the 8 threads of each row ----
    lpart += __shfl_xor_sync(0xffffffffu, lpart, 1);
    lpart += __shfl_xor_sync(0xffffffffu, lpart, 2);
    lpart += __shfl_xor_sync(0xffffffffu, lpart, 4);
    if (oct == 0) ((float*)(smem + L_OFF))[prow] = lpart;
    __syncthreads();

    // ---- epilogue: normalize + ELU + store ----
    const int row0 = rb + (lane >> 2);
    const int row1 = row0 + 8;
    const float inv0 = 1.f / ((float*)(smem + L_OFF))[row0];
    const float inv1 = 1.f / ((float*)(smem + L_OFF))[row1];
    const int cbase = nq * 16 + (lane & 3) * 2;
    float* dst0 = out + ((size_t)(b * NN + i0 + row0)) * FOUT + cbase;
    float* dst1 = out + ((size_t)(b * NN + i0 + row1)) * FOUT + cbase;
#pragma unroll
    for (int g = 0; g < 2; g++) {
        float v0 = acc[g][0] * inv0, v1 = acc[g][1] * inv0;
        float v2 = acc[g][2] * inv1, v3 = acc[g][3] * inv1;
        v0 = (v0 > 0.f) ? v0 : expm1f(v0);
        v1 = (v1 > 0.f) ? v1 : expm1f(v1);
        v2 = (v2 > 0.f) ? v2 : expm1f(v2);
        v3 = (v3 > 0.f) ? v3 : expm1f(v3);
        *(float2*)(dst0 + g * 8) = make_float2(v0, v1);
        *(float2*)(dst1 + g * 8) = make_float2(v2, v3);
    }
}

// ---------------------------------------------------------------------------
extern "C" void kernel_launch(void* const* d_in, const int* in_sizes, int n_in,
                              void* d_out, int out_size) {
    const float* h   = (const float*)d_in[0];   // [8,2048,256]
    const float* W   = (const float*)d_in[1];   // [64,256]
    const float* a   = (const float*)d_in[2];   // [128,1]
    const int*   adj = (const int*)d_in[3];     // [8,2048,2048]
    float* out = (float*)d_out;                 // [8,2048,64]

    wh_gemm<<<BATCH * NN / 64, 256>>>(h, W);
    e_kernel<<<64, 256>>>(a);
    cudaFuncSetAttribute(attn_mma, cudaFuncAttributeMaxDynamicSharedMemorySize, SMEM_SZ);
    attn_mma<<<dim3(NN / 64, BATCH), 512, SMEM_SZ>>>(adj, out);
}

// round 15
// speedup vs baseline: 1.1117x; 1.1117x over previous
#include <cuda_runtime.h>
#include <cuda_fp16.h>
#include <math.h>
#include <stdint.h>

#define BATCH 8
#define NN    2048
#define FIN   256
#define FOUT  64
#define LALPHA 0.2f

// ---------------- scratch (__device__ globals) -----------------------------
__device__ float  g_Wh[BATCH * NN * FOUT];      // 4 MB fp32 (for e-factors)
__device__ __half g_Whh[BATCH * NN * FOUT];     // 2 MB  [b][j][o] fp16
__device__ float  g_e1[BATCH * NN];
__device__ float2 g_BD[BATCH * NN];             // (exp(e2), exp(0.2*e2))
__device__ float  g_pmax[64];

// ---------------- PTX helpers ----------------------------------------------
__device__ __forceinline__ uint32_t smem_u32(const void* p) {
    uint32_t a;
    asm("{ .reg .u64 t; cvta.to.shared.u64 t, %1; cvt.u32.u64 %0, t; }" : "=r"(a) : "l"(p));
    return a;
}
__device__ __forceinline__ void ldsm_x4(uint32_t* r, uint32_t a) {
    asm volatile("ldmatrix.sync.aligned.m8n8.x4.shared.b16 {%0,%1,%2,%3}, [%4];"
                 : "=r"(r[0]), "=r"(r[1]), "=r"(r[2]), "=r"(r[3]) : "r"(a));
}
__device__ __forceinline__ void ldsm_x4_t(uint32_t* r, uint32_t a) {
    asm volatile("ldmatrix.sync.aligned.m8n8.x4.trans.shared.b16 {%0,%1,%2,%3}, [%4];"
                 : "=r"(r[0]), "=r"(r[1]), "=r"(r[2]), "=r"(r[3]) : "r"(a));
}
__device__ __forceinline__ void mma16816(float* c, const uint32_t* a,
                                         uint32_t b0, uint32_t b1) {
    asm volatile("mma.sync.aligned.m16n8k16.row.col.f32.f16.f16.f32 "
                 "{%0,%1,%2,%3}, {%4,%5,%6,%7}, {%8,%9}, {%0,%1,%2,%3};"
                 : "+f"(c[0]), "+f"(c[1]), "+f"(c[2]), "+f"(c[3])
                 : "r"(a[0]), "r"(a[1]), "r"(a[2]), "r"(a[3]), "r"(b0), "r"(b1));
}
__device__ __forceinline__ void cp_async16(uint32_t dst, const void* src) {
    asm volatile("cp.async.ca.shared.global [%0], [%1], 16;" :: "r"(dst), "l"(src));
}

// ---------------------------------------------------------------------------
// Kernel A: Wh = h @ W^T  (16384x64x256). 64-row tiles, 256 threads, grid 256.
// ---------------------------------------------------------------------------
#define AK 32
__global__ __launch_bounds__(256) void wh_gemm(const float* __restrict__ h,
                                               const float* __restrict__ W) {
    __shared__ float shT[AK][68];
    __shared__ float sWT[AK][68];
    const int t    = threadIdx.x;
    const int row0 = blockIdx.x * 64;
    const int rg   = t >> 4;
    const int cgA  = t & 15;

    float acc[4][4];
#pragma unroll
    for (int r = 0; r < 4; r++)
#pragma unroll
        for (int c = 0; c < 4; c++) acc[r][c] = 0.f;

    for (int k0 = 0; k0 < FIN; k0 += AK) {
        __syncthreads();
        int idx = t;
#pragma unroll
        for (int u = 0; u < 2; u++, idx += 256) {
            int r = idx >> 3, kq = idx & 7;
            float4 v = *(const float4*)(h + (size_t)(row0 + r) * FIN + k0 + kq * 4);
            shT[kq*4+0][r] = v.x; shT[kq*4+1][r] = v.y;
            shT[kq*4+2][r] = v.z; shT[kq*4+3][r] = v.w;
        }
        idx = t;
#pragma unroll
        for (int u = 0; u < 2; u++, idx += 256) {
            int o = idx >> 3, kq = idx & 7;
            float4 v = *(const float4*)(W + (size_t)o * FIN + k0 + kq * 4);
            sWT[kq*4+0][o] = v.x; sWT[kq*4+1][o] = v.y;
            sWT[kq*4+2][o] = v.z; sWT[kq*4+3][o] = v.w;
        }
        __syncthreads();

#pragma unroll
        for (int k = 0; k < AK; k++) {
            float4 hv = *(const float4*)&shT[k][rg * 4];
            float4 wv = *(const float4*)&sWT[k][cgA * 4];
            float hr[4] = {hv.x, hv.y, hv.z, hv.w};
            float wc[4] = {wv.x, wv.y, wv.z, wv.w};
#pragma unroll
            for (int r = 0; r < 4; r++)
#pragma unroll
                for (int c = 0; c < 4; c++) acc[r][c] = fmaf(hr[r], wc[c], acc[r][c]);
        }
    }

#pragma unroll
    for (int r = 0; r < 4; r++) {
        const size_t row = row0 + rg * 4 + r;
        *(float4*)(g_Wh + row * FOUT + cgA * 4) =
            make_float4(acc[r][0], acc[r][1], acc[r][2], acc[r][3]);
        __half2 h01 = __float22half2_rn(make_float2(acc[r][0], acc[r][1]));
        __half2 h23 = __float22half2_rn(make_float2(acc[r][2], acc[r][3]));
        *(uint2*)(g_Whh + row * FOUT + cgA * 4) = make_uint2(*(unsigned*)&h01, *(unsigned*)&h23);
    }
}

// ---------------------------------------------------------------------------
// Kernel E: e1, (B,D)=exp factors, partial max(e2). 64 blocks, 256 threads.
// ---------------------------------------------------------------------------
__global__ __launch_bounds__(256) void e_kernel(const float* __restrict__ a) {
    const int blk = blockIdx.x, t = threadIdx.x;
    const int bb = blk >> 3, ch = blk & 7;
    __shared__ float sa1[FOUT], sa2[FOUT], smax[256];
    if (t < FOUT) sa1[t] = a[t];
    else if (t < 2 * FOUT) sa2[t - FOUT] = a[t];
    __syncthreads();

    const int row = bb * NN + ch * 256 + t;
    const float4* wh = (const float4*)(g_Wh + (size_t)row * FOUT);
    float e1 = 0.f, e2 = 0.f;
#pragma unroll
    for (int q = 0; q < 16; q++) {
        float4 v = wh[q];
        e1 = fmaf(v.x, sa1[q*4+0], fmaf(v.y, sa1[q*4+1], fmaf(v.z, sa1[q*4+2], fmaf(v.w, sa1[q*4+3], e1))));
        e2 = fmaf(v.x, sa2[q*4+0], fmaf(v.y, sa2[q*4+1], fmaf(v.z, sa2[q*4+2], fmaf(v.w, sa2[q*4+3], e2))));
    }
    g_e1[row] = e1;
    g_BD[row] = make_float2(__expf(e2), __expf(LALPHA * e2));
    smax[t] = e2; __syncthreads();
    for (int s = 128; s > 0; s >>= 1) {
        if (t < s) smax[t] = fmaxf(smax[t], smax[t + s]);
        __syncthreads();
    }
    if (t == 0) g_pmax[blk] = smax[0];
}

// ---------------------------------------------------------------------------
// Kernel C: fused masked softmax @ Wh via mma.sync (single-term fp16).
// adj packed in-block to smem bitmask (pipelined); Wh double-buffered cp.async.
// Block = (b, 64-row tile): grid (32,8)=256, 512 thr, 2 blocks/SM.
// ---------------------------------------------------------------------------
#define PH_OFF   0               // P fp16 tile: 64 x 72 halves  = 9216 B
#define WH_OFF   9216            // 2 bufs x 9216                = 18432 B
#define BD_OFF   27648           // 1024 float4                  = 16384 B
#define BITS_OFF 44032           // 64 rows x 272 B              = 17408 B
#define L_OFF    61440           // 64 floats
#define SMEM_SZ  61696

__global__ __launch_bounds__(512, 2) void attn_mma(const int* __restrict__ adj,
                                                   float* __restrict__ out) {
    extern __shared__ char smem[];
    const uint32_t sb = smem_u32(smem);

    const int t    = threadIdx.x;
    const int wid  = t >> 5;
    const int lane = t & 31;
    const int b    = blockIdx.y;
    const int i0   = blockIdx.x * 64;

    const int prow = t >> 3;
    const int oct  = t & 7;

    {   // (B,D) factors -> smem (1024 float4, 2 per thread)
        const float4* src = (const float4*)(g_BD + (size_t)b * NN);
        float4* dst = (float4*)(smem + BD_OFF);
#pragma unroll
        for (int u = 0; u < 2; u++) dst[t + u * 512] = src[t + u * 512];
    }
    const float e1r = g_e1[b * NN + i0 + prow];
    float e2m = -3.0e38f;
#pragma unroll
    for (int k = 0; k < 8; k++) e2m = fmaxf(e2m, g_pmax[b * 8 + k]);
    float Mr = e1r + e2m;
    Mr = (Mr > 0.f) ? Mr : LALPHA * Mr;
    const float Ar = __expf(e1r - Mr);
    const float Cr = __expf(LALPHA * e1r - Mr);
    const float Tr = __expf(-e1r);

    // ---- pack chunk 0 of adj into smem bitmask (warp w: rows 4w..4w+3) ----
    {
#pragma unroll 1
        for (int kb = 0; kb < 64; kb += 8) {
            int pk[8];
#pragma unroll
            for (int m = 0; m < 8; m++) {
                int k = kb + m;
                pk[m] = adj[(size_t)(b*NN + i0 + wid*4 + (k >> 4)) * NN + (k & 15) * 32 + lane];
            }
#pragma unroll
            for (int m = 0; m < 8; m++) {
                int k = kb + m;
                uint32_t msk = __ballot_sync(0xffffffffu, pk[m] > 0);
                if (lane == 0)
                    *(uint32_t*)(smem + BITS_OFF + (wid*4 + (k >> 4)) * 272 + (k & 15) * 4) = msk;
            }
        }
    }

    const int wjr = t >> 3;
    const int wjc = (t & 7) * 8;
    const uint32_t wh_sdst = (uint32_t)((wjr * 72 + wjc) * 2);

    {   // cp.async Wh tile 0 -> buf 0
        const size_t gsrc = ((size_t)(b * NN) + wjr) * FOUT + wjc;
        cp_async16(sb + WH_OFF + wh_sdst, g_Whh + gsrc);
        asm volatile("cp.async.commit_group;");
    }

    float acc[2][4];
#pragma unroll
    for (int g = 0; g < 2; g++)
#pragma unroll
        for (int q = 0; q < 4; q++) acc[g][q] = 0.f;
    float lpart = 0.f;

    const int slab = wid >> 2;
    const int nq   = wid & 3;
    const int rb   = slab * 16;
    const int m8 = lane >> 3, r8 = lane & 7;
    const uint32_t a_off = (uint32_t)(((rb + r8 + 8 * (m8 & 1)) * 72 + 8 * (m8 >> 1)) * 2);
    const uint32_t b_off = (uint32_t)(((r8 + 8 * (m8 & 1)) * 72 + 8 * (m8 >> 1)) * 2);
    const uint32_t p_off = (uint32_t)((prow * 72 + oct * 8) * 2);

    __syncthreads();

    for (int jt = 0; jt < 32; jt++) {
        const int j0 = jt * 64;
        const int s  = jt & 1;
        const int c  = (jt >> 3) + 1;
        const int kbase = (jt & 7) * 8;

        // ---- 1. issue pack loads for next chunk ----
        int pk[8];
        if (c < 4) {
#pragma unroll
            for (int m = 0; m < 8; m++) {
                int k = kbase + m;
                pk[m] = adj[(size_t)(b*NN + i0 + wid*4 + (k >> 4)) * NN
                            + c * 512 + (k & 15) * 32 + lane];
            }
        }

        // ---- 2. cp.async next Wh tile ----
        if (jt < 31) {
            const size_t gsrc = ((size_t)(b * NN) + (jt + 1) * 64 + wjr) * FOUT + wjc;
            cp_async16(sb + WH_OFF + ((jt + 1) & 1) * 9216 + wh_sdst, g_Whh + gsrc);
            asm volatile("cp.async.commit_group;");
        }

        // ---- 3. P phase: 8 probs (no exp, mask = smem bit) ----
        {
            const uint32_t mbyte =
                *(const unsigned char*)(smem + BITS_OFF + prow * 272 + jt * 8 + oct);
            const float4* bdq = (const float4*)(smem + BD_OFF) + (j0 >> 1) + oct * 4;
            float pq[8];
#pragma unroll
            for (int cc = 0; cc < 2; cc++) {
                float4 bd0 = bdq[cc * 2];
                float4 bd1 = bdq[cc * 2 + 1];
                float Bv[4] = {bd0.x, bd0.z, bd1.x, bd1.z};
                float Dv[4] = {bd0.y, bd0.w, bd1.y, bd1.w};
#pragma unroll
                for (int q = 0; q < 4; q++) {
                    bool hi = Bv[q] > Tr;
                    float p = (hi ? Ar : Cr) * (hi ? Bv[q] : Dv[q]);
                    p = ((mbyte >> (cc * 4 + q)) & 1) ? p : 0.f;
                    pq[cc * 4 + q] = p;
                    lpart += p;
                }
            }
            unsigned vh[4];
#pragma unroll
            for (int q = 0; q < 4; q++) {
                __half2 hh = __float22half2_rn(make_float2(pq[2*q], pq[2*q+1]));
                vh[q] = *(unsigned*)&hh;
            }
            *(uint4*)(smem + PH_OFF + p_off) = make_uint4(vh[0], vh[1], vh[2], vh[3]);
        }

        // ---- 4. ballots for next chunk -> bitmask smem ----
        if (c < 4) {
#pragma unroll
            for (int m = 0; m < 8; m++) {
                int k = kbase + m;
                uint32_t msk = __ballot_sync(0xffffffffu, pk[m] > 0);
                if (lane == 0)
                    *(uint32_t*)(smem + BITS_OFF + (wid*4 + (k >> 4)) * 272
                                 + (c * 16 + (k & 15)) * 4) = msk;
            }
        }

        // ---- 5. wait Wh[jt], barrier ----
        if (jt < 31) asm volatile("cp.async.wait_group 1;");
        else         asm volatile("cp.async.wait_group 0;");
        __syncthreads();

        // ---- 6. mma phase: 4 k-chunks x 1 n-quarter, single term ----
        const uint32_t whh = sb + WH_OFF + s * 9216;
#pragma unroll
        for (int kk = 0; kk < 4; kk++) {
            uint32_t ah[4];
            ldsm_x4(ah, sb + PH_OFF + a_off + kk * 32);
            uint32_t bh[4];
            ldsm_x4_t(bh, whh + b_off + kk * (16 * 144) + nq * 32);
            mma16816(acc[0], ah, bh[0], bh[1]);
            mma16816(acc[1], ah, bh[2], bh[3]);
        }
        __syncthreads();
    }

    // ---- denominators ----
    lpart += __shfl_xor_sync(0xffffffffu, lpart, 1);
    lpart += __shfl_xor_sync(0xffffffffu, lpart, 2);
    lpart += __shfl_xor_sync(0xffffffffu, lpart, 4);
    if (oct == 0) ((float*)(smem + L_OFF))[prow] = lpart;
    __syncthreads();

    // ---- epilogue: normalize + ELU + store ----
    const int row0 = rb + (lane >> 2);
    const int row1 = row0 + 8;
    const float inv0 = 1.f / ((float*)(smem + L_OFF))[row0];
    const float inv1 = 1.f / ((float*)(smem + L_OFF))[row1];
    const int cbase = nq * 16 + (lane & 3) * 2;
    float* dst0 = out + ((size_t)(b * NN + i0 + row0)) * FOUT + cbase;
    float* dst1 = out + ((size_t)(b * NN + i0 + row1)) * FOUT + cbase;
#pragma unroll
    for (int g = 0; g < 2; g++) {
        float v0 = acc[g][0] * inv0, v1 = acc[g][1] * inv0;
        float v2 = acc[g][2] * inv1, v3 = acc[g][3] * inv1;
        v0 = (v0 > 0.f) ? v0 : expm1f(v0);
        v1 = (v1 > 0.f) ? v1 : expm1f(v1);
        v2 = (v2 > 0.f) ? v2 : expm1f(v2);
        v3 = (v3 > 0.f) ? v3 : expm1f(v3);
        *(float2*)(dst0 + g * 8) = make_float2(v0, v1);
        *(float2*)(dst1 + g * 8) = make_float2(v2, v3);
    }
}

// ---------------------------------------------------------------------------
extern "C" void kernel_launch(void* const* d_in, const int* in_sizes, int n_in,
                              void* d_out, int out_size) {
    const float* h   = (const float*)d_in[0];   // [8,2048,256]
    const float* W   = (const float*)d_in[1];   // [64,256]
    const float* a   = (const float*)d_in[2];   // [128,1]
    const int*   adj = (const int*)d_in[3];     // [8,2048,2048]
    float* out = (float*)d_out;                 // [8,2048,64]

    wh_gemm<<<BATCH * NN / 64, 256>>>(h, W);
    e_kernel<<<64, 256>>>(a);
    cudaFuncSetAttribute(attn_mma, cudaFuncAttributeMaxDynamicSharedMemorySize, SMEM_SZ);
    attn_mma<<<dim3(NN / 64, BATCH), 512, SMEM_SZ>>>(adj, out);
}

// round 16
// speedup vs baseline: 1.3618x; 1.2249x over previous
#include <cuda_runtime.h>
#include <cuda_fp16.h>
#include <math.h>
#include <stdint.h>

#define BATCH 8
#define NN    2048
#define FIN   256
#define FOUT  64
#define LALPHA 0.2f

// ---------------- scratch (__device__ globals) -----------------------------
__device__ float  g_Wh[BATCH * NN * FOUT];      // 4 MB fp32 (for e-factors)
__device__ __half g_Whh[BATCH * NN * FOUT];     // 2 MB  [b][j][o] fp16
__device__ float  g_e1[BATCH * NN];
__device__ float2 g_BD[BATCH * NN];             // (exp(e2), exp(0.2*e2))
__device__ float  g_pmax[64];

// ---------------- PTX helpers ----------------------------------------------
__device__ __forceinline__ uint32_t smem_u32(const void* p) {
    uint32_t a;
    asm("{ .reg .u64 t; cvta.to.shared.u64 t, %1; cvt.u32.u64 %0, t; }" : "=r"(a) : "l"(p));
    return a;
}
__device__ __forceinline__ void ldsm_x4_t(uint32_t* r, uint32_t a) {
    asm volatile("ldmatrix.sync.aligned.m8n8.x4.trans.shared.b16 {%0,%1,%2,%3}, [%4];"
                 : "=r"(r[0]), "=r"(r[1]), "=r"(r[2]), "=r"(r[3]) : "r"(a));
}
__device__ __forceinline__ void mma16816(float* c, const uint32_t* a,
                                         uint32_t b0, uint32_t b1) {
    asm volatile("mma.sync.aligned.m16n8k16.row.col.f32.f16.f16.f32 "
                 "{%0,%1,%2,%3}, {%4,%5,%6,%7}, {%8,%9}, {%0,%1,%2,%3};"
                 : "+f"(c[0]), "+f"(c[1]), "+f"(c[2]), "+f"(c[3])
                 : "r"(a[0]), "r"(a[1]), "r"(a[2]), "r"(a[3]), "r"(b0), "r"(b1));
}
__device__ __forceinline__ void cp_async16(uint32_t dst, const void* src) {
    asm volatile("cp.async.ca.shared.global [%0], [%1], 16;" :: "r"(dst), "l"(src));
}

// ---------------------------------------------------------------------------
// Kernel A: Wh = h @ W^T  (16384x64x256). 64-row tiles, 256 threads, grid 256.
// ---------------------------------------------------------------------------
#define AK 32
__global__ __launch_bounds__(256) void wh_gemm(const float* __restrict__ h,
                                               const float* __restrict__ W) {
    __shared__ float shT[AK][68];
    __shared__ float sWT[AK][68];
    const int t    = threadIdx.x;
    const int row0 = blockIdx.x * 64;
    const int rg   = t >> 4;
    const int cgA  = t & 15;

    float acc[4][4];
#pragma unroll
    for (int r = 0; r < 4; r++)
#pragma unroll
        for (int c = 0; c < 4; c++) acc[r][c] = 0.f;

    for (int k0 = 0; k0 < FIN; k0 += AK) {
        __syncthreads();
        int idx = t;
#pragma unroll
        for (int u = 0; u < 2; u++, idx += 256) {
            int r = idx >> 3, kq = idx & 7;
            float4 v = *(const float4*)(h + (size_t)(row0 + r) * FIN + k0 + kq * 4);
            shT[kq*4+0][r] = v.x; shT[kq*4+1][r] = v.y;
            shT[kq*4+2][r] = v.z; shT[kq*4+3][r] = v.w;
        }
        idx = t;
#pragma unroll
        for (int u = 0; u < 2; u++, idx += 256) {
            int o = idx >> 3, kq = idx & 7;
            float4 v = *(const float4*)(W + (size_t)o * FIN + k0 + kq * 4);
            sWT[kq*4+0][o] = v.x; sWT[kq*4+1][o] = v.y;
            sWT[kq*4+2][o] = v.z; sWT[kq*4+3][o] = v.w;
        }
        __syncthreads();

#pragma unroll
        for (int k = 0; k < AK; k++) {
            float4 hv = *(const float4*)&shT[k][rg * 4];
            float4 wv = *(const float4*)&sWT[k][cgA * 4];
            float hr[4] = {hv.x, hv.y, hv.z, hv.w};
            float wc[4] = {wv.x, wv.y, wv.z, wv.w};
#pragma unroll
            for (int r = 0; r < 4; r++)
#pragma unroll
                for (int c = 0; c < 4; c++) acc[r][c] = fmaf(hr[r], wc[c], acc[r][c]);
        }
    }

#pragma unroll
    for (int r = 0; r < 4; r++) {
        const size_t row = row0 + rg * 4 + r;
        *(float4*)(g_Wh + row * FOUT + cgA * 4) =
            make_float4(acc[r][0], acc[r][1], acc[r][2], acc[r][3]);
        __half2 h01 = __float22half2_rn(make_float2(acc[r][0], acc[r][1]));
        __half2 h23 = __float22half2_rn(make_float2(acc[r][2], acc[r][3]));
        *(uint2*)(g_Whh + row * FOUT + cgA * 4) = make_uint2(*(unsigned*)&h01, *(unsigned*)&h23);
    }
}

// ---------------------------------------------------------------------------
// Kernel E: e1, (B,D)=exp factors, partial max(e2). 64 blocks, 256 threads.
// ---------------------------------------------------------------------------
__global__ __launch_bounds__(256) void e_kernel(const float* __restrict__ a) {
    const int blk = blockIdx.x, t = threadIdx.x;
    const int bb = blk >> 3, ch = blk & 7;
    __shared__ float sa1[FOUT], sa2[FOUT], smax[256];
    if (t < FOUT) sa1[t] = a[t];
    else if (t < 2 * FOUT) sa2[t - FOUT] = a[t];
    __syncthreads();

    const int row = bb * NN + ch * 256 + t;
    const float4* wh = (const float4*)(g_Wh + (size_t)row * FOUT);
    float e1 = 0.f, e2 = 0.f;
#pragma unroll
    for (int q = 0; q < 16; q++) {
        float4 v = wh[q];
        e1 = fmaf(v.x, sa1[q*4+0], fmaf(v.y, sa1[q*4+1], fmaf(v.z, sa1[q*4+2], fmaf(v.w, sa1[q*4+3], e1))));
        e2 = fmaf(v.x, sa2[q*4+0], fmaf(v.y, sa2[q*4+1], fmaf(v.z, sa2[q*4+2], fmaf(v.w, sa2[q*4+3], e2))));
    }
    g_e1[row] = e1;
    g_BD[row] = make_float2(__expf(e2), __expf(LALPHA * e2));
    smax[t] = e2; __syncthreads();
    for (int s = 128; s > 0; s >>= 1) {
        if (t < s) smax[t] = fmaxf(smax[t], smax[t + s]);
        __syncthreads();
    }
    if (t == 0) g_pmax[blk] = smax[0];
}

// ---------------------------------------------------------------------------
// Kernel C: fused masked softmax @ Wh. P computed DIRECTLY in mma A-fragment
// registers (no P smem, no ldsm-A, no P barrier). Warp = 16 rows x 64 o.
// Warp-private bitmask pack (interleaved layout: ballot q-bit l == adj bit
// j = grp*128 + l*4 + q). One barrier/tile (Wh buffer rotation only).
// Block: 128 thr / 4 warps / 64 rows. Grid (32,8)=256.
// ---------------------------------------------------------------------------
#define WH_OFF   0               // 2 bufs x 64x72 halves       = 18432 B
#define BD_OFF   18432           // 1024 float4                 = 16384 B
#define BITS_OFF 34816           // 64 rows x 272 B             = 17408 B
#define SMEM_SZ  52224

__global__ __launch_bounds__(128) void attn_mma(const int* __restrict__ adj,
                                                float* __restrict__ out) {
    extern __shared__ char smem[];
    const uint32_t sb = smem_u32(smem);

    const int t    = threadIdx.x;
    const int wid  = t >> 5;
    const int lane = t & 31;
    const int b    = blockIdx.y;
    const int i0   = blockIdx.x * 64;
    const int rb   = wid * 16;
    const int g    = lane >> 2, tc = lane & 3;
    const int m8   = lane >> 3, r8 = lane & 7;

    {   // (B,D) factors -> smem (1024 float4, 8 per thread)
        const float4* src = (const float4*)(g_BD + (size_t)b * NN);
        float4* dst = (float4*)(smem + BD_OFF);
#pragma unroll
        for (int u = 0; u < 8; u++) dst[t + u * 128] = src[t + u * 128];
    }
    float e2m = -3.0e38f;
#pragma unroll
    for (int k = 0; k < 8; k++) e2m = fmaxf(e2m, g_pmax[b * 8 + k]);
    const float e1_0 = g_e1[b * NN + i0 + rb + g];
    const float e1_1 = g_e1[b * NN + i0 + rb + g + 8];
    float M0 = e1_0 + e2m; M0 = (M0 > 0.f) ? M0 : LALPHA * M0;
    float M1 = e1_1 + e2m; M1 = (M1 > 0.f) ? M1 : LALPHA * M1;
    const float A0 = __expf(e1_0 - M0), C0 = __expf(LALPHA * e1_0 - M0);
    const float A1 = __expf(e1_1 - M1), C1 = __expf(LALPHA * e1_1 - M1);

    const int4* adj4 = (const int4*)adj;

    // ---- pack chunk 0 (warp-private: own 16 rows, j 0..511) ----
#pragma unroll 4
    for (int it = 0; it < 64; it++) {
        const int r = it >> 2, grp = it & 3;
        int4 v = adj4[((size_t)(b * NN + i0 + rb + r)) * 512 + grp * 32 + lane];
        uint32_t b0 = __ballot_sync(0xffffffffu, v.x > 0);
        uint32_t b1 = __ballot_sync(0xffffffffu, v.y > 0);
        uint32_t b2 = __ballot_sync(0xffffffffu, v.z > 0);
        uint32_t b3 = __ballot_sync(0xffffffffu, v.w > 0);
        if (lane == 0)
            *(uint4*)(smem + BITS_OFF + (rb + r) * 272 + grp * 16) = make_uint4(b0, b1, b2, b3);
    }

    {   // cp.async Wh tile 0 -> buf 0 (4 x 16B per thread)
#pragma unroll
        for (int u = 0; u < 4; u++) {
            const int idx = u * 128 + t, row = idx >> 3, c8 = idx & 7;
            cp_async16(sb + WH_OFF + (row * 72 + c8 * 8) * 2,
                       g_Whh + ((size_t)(b * NN) + row) * 64 + c8 * 8);
        }
        asm volatile("cp.async.commit_group;");
    }

    float acc[8][4];
#pragma unroll
    for (int og = 0; og < 8; og++)
#pragma unroll
        for (int q = 0; q < 4; q++) acc[og][q] = 0.f;
    float lp0 = 0.f, lp1 = 0.f;

    const uint32_t bconst = (uint32_t)(((r8 + 8 * (m8 & 1)) * 72 + 8 * (m8 >> 1)) * 2);

    __syncthreads();   // BD + bits(chunk0) + nothing-else ready

    for (int jt = 0; jt < 32; jt++) {
        // ---- 1. pack next chunk (warp-private rows) ----
        const int c = (jt >> 3) + 1;
        if (c < 4) {
            int4 pv[8];
#pragma unroll
            for (int m = 0; m < 8; m++) {
                const int it = (jt & 7) * 8 + m, r = it >> 2, grp = it & 3;
                pv[m] = adj4[((size_t)(b * NN + i0 + rb + r)) * 512 + c * 128 + grp * 32 + lane];
            }
#pragma unroll
            for (int m = 0; m < 8; m++) {
                const int it = (jt & 7) * 8 + m, r = it >> 2, grp = it & 3;
                uint32_t b0 = __ballot_sync(0xffffffffu, pv[m].x > 0);
                uint32_t b1 = __ballot_sync(0xffffffffu, pv[m].y > 0);
                uint32_t b2 = __ballot_sync(0xffffffffu, pv[m].z > 0);
                uint32_t b3 = __ballot_sync(0xffffffffu, pv[m].w > 0);
                if (lane == 0)
                    *(uint4*)(smem + BITS_OFF + (rb + r) * 272 + (c * 4 + grp) * 16) =
                        make_uint4(b0, b1, b2, b3);
            }
        }

        // ---- 2. P -> A-fragments (registers; p = max(A*B, C*D), masked) ----
        uint32_t Af[4][4];
        {
            const uint4 bv0 = *(const uint4*)(smem + BITS_OFF + (rb + g) * 272 + (jt >> 1) * 16);
            const uint4 bv1 = *(const uint4*)(smem + BITS_OFF + (rb + g + 8) * 272 + (jt >> 1) * 16);
            const uint32_t we0 = (tc & 1) ? bv0.z : bv0.x, wo0 = (tc & 1) ? bv0.w : bv0.y;
            const uint32_t we1 = (tc & 1) ? bv1.z : bv1.x, wo1 = (tc & 1) ? bv1.w : bv1.y;
            const float4* bd4 = (const float4*)(smem + BD_OFF) + jt * 32 + tc;
#pragma unroll
            for (int kk = 0; kk < 4; kk++) {
                const int l0 = (jt & 1) * 16 + kk * 4 + (tc >> 1);
                const float4 u4 = bd4[kk * 8];       // {B(j),D(j),B(j+1),D(j+1)}
                const float4 v4 = bd4[kk * 8 + 4];   // j+8, j+9
                float p00 = ((we0 >> l0) & 1)       ? fmaxf(A0 * u4.x, C0 * u4.y) : 0.f;
                float p01 = ((wo0 >> l0) & 1)       ? fmaxf(A0 * u4.z, C0 * u4.w) : 0.f;
                float p08 = ((we0 >> (l0 + 2)) & 1) ? fmaxf(A0 * v4.x, C0 * v4.y) : 0.f;
                float p09 = ((wo0 >> (l0 + 2)) & 1) ? fmaxf(A0 * v4.z, C0 * v4.w) : 0.f;
                float p10 = ((we1 >> l0) & 1)       ? fmaxf(A1 * u4.x, C1 * u4.y) : 0.f;
                float p11 = ((wo1 >> l0) & 1)       ? fmaxf(A1 * u4.z, C1 * u4.w) : 0.f;
                float p18 = ((we1 >> (l0 + 2)) & 1) ? fmaxf(A1 * v4.x, C1 * v4.y) : 0.f;
                float p19 = ((wo1 >> (l0 + 2)) & 1) ? fmaxf(A1 * v4.z, C1 * v4.w) : 0.f;
                lp0 += (p00 + p01) + (p08 + p09);
                lp1 += (p10 + p11) + (p18 + p19);
                __half2 h;
                h = __float22half2_rn(make_float2(p00, p01)); Af[kk][0] = *(uint32_t*)&h;
                h = __float22half2_rn(make_float2(p10, p11)); Af[kk][1] = *(uint32_t*)&h;
                h = __float22half2_rn(make_float2(p08, p09)); Af[kk][2] = *(uint32_t*)&h;
                h = __float22half2_rn(make_float2(p18, p19)); Af[kk][3] = *(uint32_t*)&h;
            }
        }

        // ---- 3-4. Wh[jt] ready + single barrier (also frees buf jt-1) ----
        asm volatile("cp.async.wait_group 0;");
        __syncthreads();

        // ---- 5. prefetch Wh[jt+1] ----
        if (jt < 31) {
#pragma unroll
            for (int u = 0; u < 4; u++) {
                const int idx = u * 128 + t, row = idx >> 3, c8 = idx & 7;
                cp_async16(sb + WH_OFF + ((jt + 1) & 1) * 9216 + (row * 72 + c8 * 8) * 2,
                           g_Whh + ((size_t)(b * NN) + (jt + 1) * 64 + row) * 64 + c8 * 8);
            }
            asm volatile("cp.async.commit_group;");
        }

        // ---- 6. MMA: 4 k-chunks x 4 o-quarters ----
        const uint32_t whb = sb + WH_OFF + (jt & 1) * 9216 + bconst;
#pragma unroll
        for (int kk = 0; kk < 4; kk++) {
#pragma unroll
            for (int q = 0; q < 4; q++) {
                uint32_t bh[4];
                ldsm_x4_t(bh, whb + kk * 2304 + q * 32);
                mma16816(acc[2 * q],     Af[kk], bh[0], bh[1]);
                mma16816(acc[2 * q + 1], Af[kk], bh[2], bh[3]);
            }
        }
    }

    // ---- denominators: quad-reduce (lanes share row via g) ----
    lp0 += __shfl_xor_sync(0xffffffffu, lp0, 1);
    lp0 += __shfl_xor_sync(0xffffffffu, lp0, 2);
    lp1 += __shfl_xor_sync(0xffffffffu, lp1, 1);
    lp1 += __shfl_xor_sync(0xffffffffu, lp1, 2);
    const float inv0 = 1.f / lp0, inv1 = 1.f / lp1;

    // ---- epilogue: normalize + ELU + store ----
    float* d0 = out + ((size_t)(b * NN + i0 + rb + g)) * FOUT + tc * 2;
    float* d1 = out + ((size_t)(b * NN + i0 + rb + g + 8)) * FOUT + tc * 2;
#pragma unroll
    for (int og = 0; og < 8; og++) {
        float v0 = acc[og][0] * inv0, v1 = acc[og][1] * inv0;
        float v2 = acc[og][2] * inv1, v3 = acc[og][3] * inv1;
        v0 = (v0 > 0.f) ? v0 : expm1f(v0);
        v1 = (v1 > 0.f) ? v1 : expm1f(v1);
        v2 = (v2 > 0.f) ? v2 : expm1f(v2);
        v3 = (v3 > 0.f) ? v3 : expm1f(v3);
        *(float2*)(d0 + og * 8) = make_float2(v0, v1);
        *(float2*)(d1 + og * 8) = make_float2(v2, v3);
    }
}

// ---------------------------------------------------------------------------
extern "C" void kernel_launch(void* const* d_in, const int* in_sizes, int n_in,
                              void* d_out, int out_size) {
    const float* h   = (const float*)d_in[0];   // [8,2048,256]
    const float* W   = (const float*)d_in[1];   // [64,256]
    const float* a   = (const float*)d_in[2];   // [128,1]
    const int*   adj = (const int*)d_in[3];     // [8,2048,2048]
    float* out = (float*)d_out;                 // [8,2048,64]

    wh_gemm<<<BATCH * NN / 64, 256>>>(h, W);
    e_kernel<<<64, 256>>>(a);
    cudaFuncSetAttribute(attn_mma, cudaFuncAttributeMaxDynamicSharedMemorySize, SMEM_SZ);
    attn_mma<<<dim3(NN / 64, BATCH), 128, SMEM_SZ>>>(adj, out);
}